// round 13
// baseline (speedup 1.0000x reference)
#include <cuda_runtime.h>
#include <cuda_fp16.h>
#include <cstdint>

// ---------------------------------------------------------------------------
// Problem constants
// ---------------------------------------------------------------------------
#define BDIM   16
#define FH     32
#define FW     32
#define NBOX   16
#define CCH    256     // conv out channels
#define DDIM   256     // dense out
#define KDIM   768     // 16*16*3
#define M_TOT  16384   // B*32*32
#define S_ROI  7

// Scratch (static __device__ — no allocations allowed)
__device__ __half g_Wh[CCH * KDIM];          // W transposed+f16: [256 n][768 k]
__device__ __half g_A16[(size_t)M_TOT * KDIM]; // im2col f16 [16384, 768]
__device__ __half g_feat[M_TOT * CCH];       // conv+relu feat [16384, 256] f16
__device__ float  g_obj[BDIM * NBOX * CCH];  // pooled rois   [256, 256]

// ---------------------------------------------------------------------------
// helpers
// ---------------------------------------------------------------------------
__device__ __forceinline__ uint32_t smem_to_u32(const void* smem_ptr) {
    uint32_t addr;
    asm("{ .reg .u64 tmp; cvta.to.shared.u64 tmp, %1; cvt.u32.u64 %0, tmp; }"
        : "=r"(addr) : "l"(smem_ptr));
    return addr;
}
__device__ __forceinline__ void mma_f16(float* d, const uint32_t* a, const uint32_t* b) {
    asm volatile(
        "mma.sync.aligned.m16n8k16.row.col.f32.f16.f16.f32 "
        "{%0,%1,%2,%3}, {%4,%5,%6,%7}, {%8,%9}, {%0,%1,%2,%3};"
        : "+f"(d[0]), "+f"(d[1]), "+f"(d[2]), "+f"(d[3])
        : "r"(a[0]), "r"(a[1]), "r"(a[2]), "r"(a[3]), "r"(b[0]), "r"(b[1]));
}
__device__ __forceinline__ void ldsm_x4(uint32_t* r, uint32_t addr) {
    asm volatile("ldmatrix.sync.aligned.m8n8.x4.shared.b16 {%0,%1,%2,%3}, [%4];"
                 : "=r"(r[0]), "=r"(r[1]), "=r"(r[2]), "=r"(r[3]) : "r"(addr));
}
__device__ __forceinline__ void ldsm_x2(uint32_t* r, uint32_t addr) {
    asm volatile("ldmatrix.sync.aligned.m8n8.x2.shared.b16 {%0,%1}, [%0+0];"
                 : "=r"(r[0]), "=r"(r[1]) : "r"(addr));
}
__device__ __forceinline__ void ldsm_x2_fix(uint32_t& r0, uint32_t& r1, uint32_t addr) {
    asm volatile("ldmatrix.sync.aligned.m8n8.x2.shared.b16 {%0,%1}, [%2];"
                 : "=r"(r0), "=r"(r1) : "r"(addr));
}
__device__ __forceinline__ void cp16(uint32_t smem_dst, const void* gsrc) {
    asm volatile("cp.async.cg.shared.global [%0], [%1], 16;"
                 :: "r"(smem_dst), "l"(gsrc));
}
#define CP_COMMIT() asm volatile("cp.async.commit_group;" ::: "memory")
#define CP_WAIT1()  asm volatile("cp.async.wait_group 1;"  ::: "memory")
#define CP_WAIT0()  asm volatile("cp.async.wait_group 0;"  ::: "memory")

// ---------------------------------------------------------------------------
// 0a) W prepass: W[768,256] f32 -> g_Wh[256 n][768 k] f16 (transpose+convert)
// ---------------------------------------------------------------------------
__global__ __launch_bounds__(256) void wprep_kernel(const float* __restrict__ W) {
    __shared__ float t[32][33];
    int kb = blockIdx.x * 32, nb = blockIdx.y * 32;
    int tx = threadIdx.x & 31, ty = threadIdx.x >> 5;   // 32 x 8
    #pragma unroll
    for (int i = 0; i < 32; i += 8)
        t[ty + i][tx] = W[(kb + ty + i) * CCH + nb + tx];
    __syncthreads();
    #pragma unroll
    for (int i = 0; i < 32; i += 8)
        g_Wh[(nb + ty + i) * KDIM + kb + tx] = __float2half_rn(t[tx][ty + i]);
}

// ---------------------------------------------------------------------------
// 0b) im2col + f16 convert: img f32 -> g_A16[16384, 768] f16.
//     One thread = 8 halves (16B store). k runs of 8 never cross a 48-float
//     pixel run (8 | 48), so the 8 source floats are contiguous.
// ---------------------------------------------------------------------------
__global__ __launch_bounds__(256) void im2col16_kernel(const float* __restrict__ img) {
    int id = blockIdx.x * blockDim.x + threadIdx.x;     // one 8-half chunk
    int hidx = id * 8;
    int m = hidx / KDIM;
    int k = hidx - m * KDIM;
    int b  = m >> 10;
    int oy = (m >> 5) & 31;
    int ox = m & 31;
    int ky  = k / 48;
    int rem = k - ky * 48;
    const float4* src = (const float4*)(
        img + (size_t)((b * 512 + oy * 16 + ky) * 512 + ox * 16) * 3 + rem);
    float4 v0 = src[0];
    float4 v1 = src[1];
    __half2 h[4];
    h[0] = __floats2half2_rn(v0.x, v0.y);
    h[1] = __floats2half2_rn(v0.z, v0.w);
    h[2] = __floats2half2_rn(v1.x, v1.y);
    h[3] = __floats2half2_rn(v1.z, v1.w);
    *(uint4*)&g_A16[hidx] = *(uint4*)h;
}

// ---------------------------------------------------------------------------
// 1) Conv-as-GEMM: f16 A from g_A16, f16 B from g_Wh, ldmatrix fragments,
//    3-stage cp.async, one barrier per chunk. CTA 128x128, 8 warps 64x32.
// ---------------------------------------------------------------------------
#define BK      32                   // k halves per chunk
#define NCH     (KDIM / BK)          // 24
#define LDH     40                   // halves per SMEM row (32 data + 8 pad)
#define ROWB    (LDH * 2)            // 80 bytes per row
#define A_BYTES (128 * ROWB)         // 10240
#define B_BYTES (128 * ROWB)         // 10240
#define STG_BYTES (A_BYTES + B_BYTES)// 20480
#define STAGES  3
#define SMEM_BYTES (STAGES * STG_BYTES)   // 61440

__global__ __launch_bounds__(256, 2) void conv_mma_kernel(
    const float* __restrict__ bias)    // [256]
{
    extern __shared__ char smem[];
    const uint32_t sb = smem_to_u32(smem);

    const int tid = threadIdx.x;
    const int wid = tid >> 5;
    const int lid = tid & 31;
    const int g   = lid >> 2;          // 0..7
    const int t4  = lid & 3;           // 0..3
    const int wm  = wid & 1;           // 2 warps in M
    const int wn  = wid >> 1;          // 4 warps in N

    const int n0 = blockIdx.x * 128;
    const int m0 = blockIdx.y * 128;

    // cp.async sources: A rows from g_A16, B rows from g_Wh (both f16 K-major)
    const int arow = tid >> 1;                   // A: 2 threads/row (i spans 2 rows? no)
    // We use f4 indexing below instead.

    auto issue = [&](int c) {
        const int k0 = c * BK;
        const uint32_t soff = sb + (uint32_t)(c % STAGES) * STG_BYTES;
        #pragma unroll
        for (int i = 0; i < 2; i++) {            // A: 512 cp16 total
            int f4  = tid + i * 256;             // 0..511
            int row = f4 >> 2;                   // 0..127
            int q   = f4 & 3;                    // 16B chunk (8 halves)
            cp16(soff + (uint32_t)(row * ROWB + q * 16),
                 g_A16 + (size_t)(m0 + row) * KDIM + k0 + q * 8);
        }
        #pragma unroll
        for (int i = 0; i < 2; i++) {            // B: 512 cp16 total
            int f4  = tid + i * 256;
            int row = f4 >> 2;
            int q   = f4 & 3;
            cp16(soff + (uint32_t)(A_BYTES + row * ROWB + q * 16),
                 g_Wh + (size_t)(n0 + row) * KDIM + k0 + q * 8);
        }
        CP_COMMIT();
    };

    float acc[4][4][4];
    #pragma unroll
    for (int i = 0; i < 4; i++)
        #pragma unroll
        for (int j = 0; j < 4; j++)
            #pragma unroll
            for (int r = 0; r < 4; r++) acc[i][j][r] = 0.f;

    // ldmatrix per-lane row/col selectors
    const int lrow = lid & 7;          // row within 8x8 tile
    const int lseg = lid >> 3;         // 0..3 (A x4); B x2 uses lseg&1

    issue(0); issue(1);

    for (int c = 0; c < NCH; c++) {
        if (c + 1 < NCH) CP_WAIT1(); else CP_WAIT0();
        __syncthreads();
        if (c + 2 < NCH) issue(c + 2);

        const uint32_t aBaseS = sb + (uint32_t)(c % STAGES) * STG_BYTES;
        const uint32_t bBaseS = aBaseS + A_BYTES;

        #pragma unroll
        for (int kk = 0; kk < 2; kk++) {           // two k16 steps per chunk
            const int ka = kk * 16;                // halves
            uint32_t afr[4][4], bfr[4][2];
            #pragma unroll
            for (int mi = 0; mi < 4; mi++) {
                int mr = wm * 64 + mi * 16;
                // x4 tiles: (m0-7,k0-7),(m8-15,k0-7),(m0-7,k8-15),(m8-15,k8-15)
                uint32_t addr = aBaseS
                    + (uint32_t)((mr + lrow + (lseg & 1) * 8) * ROWB
                                 + (ka + (lseg >> 1) * 8) * 2);
                ldsm_x4(afr[mi], addr);
            }
            #pragma unroll
            for (int ni = 0; ni < 4; ni++) {
                int nc = wn * 32 + ni * 8;
                // x2 tiles: (n0-7,k0-7),(n0-7,k8-15); lanes 16-31 ignored
                uint32_t addr = bBaseS
                    + (uint32_t)((nc + lrow) * ROWB
                                 + (ka + (lseg & 1) * 8) * 2);
                ldsm_x2_fix(bfr[ni][0], bfr[ni][1], addr);
            }
            #pragma unroll
            for (int mi = 0; mi < 4; mi++)
                #pragma unroll
                for (int ni = 0; ni < 4; ni++)
                    mma_f16(acc[mi][ni], afr[mi], bfr[ni]);
        }
    }

    // epilogue: bias + relu -> g_feat (f16)
    #pragma unroll
    for (int mi = 0; mi < 4; mi++) {
        #pragma unroll
        for (int ni = 0; ni < 4; ni++) {
            int m = m0 + wm * 64 + mi * 16 + g;
            int n = n0 + wn * 32 + ni * 8 + 2 * t4;
            float b0 = bias[n], b1 = bias[n + 1];
            __half2 h0 = __floats2half2_rn(fmaxf(acc[mi][ni][0] + b0, 0.f),
                                           fmaxf(acc[mi][ni][1] + b1, 0.f));
            __half2 h1 = __floats2half2_rn(fmaxf(acc[mi][ni][2] + b0, 0.f),
                                           fmaxf(acc[mi][ni][3] + b1, 0.f));
            *(__half2*)&g_feat[(size_t)m * CCH + n]       = h0;
            *(__half2*)&g_feat[(size_t)(m + 8) * CCH + n] = h1;
        }
    }
}

// ---------------------------------------------------------------------------
// 2) ROI align (bilinear, 7x7) + mean + notrack mask. 256 blocks (1 roi each).
// ---------------------------------------------------------------------------
__global__ __launch_bounds__(256) void roi_kernel(const float* __restrict__ boxes) {
    const int roi = blockIdx.x;
    const int b = roi >> 4;
    const int c = threadIdx.x;

    float4 box = *(const float4*)&boxes[roi * 4];
    float ymin = box.x, xmin = box.y, ymax = box.z, xmax = box.w;
    bool empty = (ymin == -1.f) && (xmin == -1.f) && (ymax == -1.f) && (xmax == -1.f);
    if (empty) { g_obj[roi * CCH + c] = 0.f; return; }

    int y0[S_ROI], y1[S_ROI], x0[S_ROI], x1[S_ROI];
    float wy[S_ROI], wx[S_ROI];
    #pragma unroll
    for (int i = 0; i < S_ROI; i++) {
        float step = ((float)i + 0.5f) / (float)S_ROI;
        float ys = ymin + (ymax - ymin) * step;
        float xs = xmin + (xmax - xmin) * step;
        float py = ys * (float)FH - 0.5f;
        float px = xs * (float)FW - 0.5f;
        float y0f = floorf(py), x0f = floorf(px);
        wy[i] = py - y0f;  wx[i] = px - x0f;
        int yi = (int)y0f, xi = (int)x0f;
        y0[i] = min(max(yi, 0), FH - 1);
        y1[i] = min(max(yi + 1, 0), FH - 1);
        x0[i] = min(max(xi, 0), FW - 1);
        x1[i] = min(max(xi + 1, 0), FW - 1);
    }

    const __half* fb = g_feat + (size_t)b * FH * FW * CCH;
    float acc = 0.f;
    #pragma unroll
    for (int i = 0; i < S_ROI; i++) {
        const __half* ry0 = fb + y0[i] * (FW * CCH);
        const __half* ry1 = fb + y1[i] * (FW * CCH);
        float wyi = wy[i];
        #pragma unroll
        for (int j = 0; j < S_ROI; j++) {
            float wxj = wx[j];
            float f00 = __half2float(ry0[x0[j] * CCH + c]);
            float f01 = __half2float(ry0[x1[j] * CCH + c]);
            float f10 = __half2float(ry1[x0[j] * CCH + c]);
            float f11 = __half2float(ry1[x1[j] * CCH + c]);
            acc += (1.f - wyi) * (1.f - wxj) * f00
                 + (1.f - wyi) * wxj         * f01
                 + wyi         * (1.f - wxj) * f10
                 + wyi         * wxj         * f11;
        }
    }
    g_obj[roi * CCH + c] = acc * (1.f / (S_ROI * S_ROI));
}

// ---------------------------------------------------------------------------
// 3) Dense: out[256,256] = obj[256,256] @ Wd[256,256] + bd.
//    128 blocks x 2 rows, Wd via 3-stage cp.async pipeline.
// ---------------------------------------------------------------------------
#define DK        32                          // k-rows per stage
#define DNSTG     (CCH / DK)                  // 8 stages
#define DSTG_FLT  (DK * DDIM)                 // 8192 floats / stage
#define DSMEM_BYTES ((3 * DSTG_FLT + 2 * CCH) * 4)   // 100352

__global__ __launch_bounds__(256) void dense_kernel(
    const float* __restrict__ Wd, const float* __restrict__ bd,
    float* __restrict__ out)
{
    extern __shared__ float s[];
    float* sW   = s;                          // [3][DK*DDIM]
    float* sObj = s + 3 * DSTG_FLT;           // [2][CCH]
    const uint32_t sb = smem_to_u32(s);

    const int tid = threadIdx.x;
    const int r0  = blockIdx.x * 2;

    auto issueW = [&](int st) {
        const uint32_t soff = sb + (uint32_t)(st % 3) * (DSTG_FLT * 4);
        const int k0 = st * DK;
        #pragma unroll
        for (int i = 0; i < 8; i++) {
            int f4  = tid + i * 256;           // 0..2047
            int row = f4 >> 6;                 // 0..31
            int q   = f4 & 63;
            cp16(soff + (uint32_t)(row * DDIM + q * 4) * 4,
                 Wd + (size_t)(k0 + row) * DDIM + q * 4);
        }
        CP_COMMIT();
    };

    issueW(0); issueW(1);

    sObj[tid]       = g_obj[(size_t)r0 * CCH + tid];
    sObj[CCH + tid] = g_obj[(size_t)(r0 + 1) * CCH + tid];
    const float bb = bd[tid];
    __syncthreads();

    float acc0 = 0.f, acc1 = 0.f;
    for (int st = 0; st < DNSTG; st++) {
        if (st + 1 < DNSTG) CP_WAIT1(); else CP_WAIT0();
        __syncthreads();
        if (st + 2 < DNSTG) issueW(st + 2);

        const float* w = sW + (st % 3) * DSTG_FLT;
        const int k0 = st * DK;
        #pragma unroll
        for (int k = 0; k < DK; k++) {
            float wv = w[k * DDIM + tid];
            acc0 += sObj[k0 + k] * wv;
            acc1 += sObj[CCH + k0 + k] * wv;
        }
    }

    out[(size_t)r0 * DDIM + tid]       = acc0 + bb;
    out[(size_t)(r0 + 1) * DDIM + tid] = acc1 + bb;
}

// ---------------------------------------------------------------------------
// Launch
// ---------------------------------------------------------------------------
extern "C" void kernel_launch(void* const* d_in, const int* in_sizes, int n_in,
                              void* d_out, int out_size) {
    const float* images  = (const float*)d_in[0];
    const float* bboxes  = (const float*)d_in[1];
    const float* conv_w  = (const float*)d_in[2];
    const float* conv_b  = (const float*)d_in[3];
    const float* dense_w = (const float*)d_in[4];
    const float* dense_b = (const float*)d_in[5];
    float* out = (float*)d_out;

    static bool attr_set = false;
    if (!attr_set) {
        cudaFuncSetAttribute(conv_mma_kernel,
                             cudaFuncAttributeMaxDynamicSharedMemorySize, SMEM_BYTES);
        cudaFuncSetAttribute(dense_kernel,
                             cudaFuncAttributeMaxDynamicSharedMemorySize, DSMEM_BYTES);
        attr_set = true;
    }

    dim3 wgrid(KDIM / 32, CCH / 32);     // (24, 8)
    wprep_kernel<<<wgrid, 256>>>(conv_w);

    im2col16_kernel<<<(M_TOT * KDIM / 8) / 256, 256>>>(images);

    dim3 grid(CCH / 128, M_TOT / 128);   // (2, 128)
    conv_mma_kernel<<<grid, 256, SMEM_BYTES>>>(conv_b);

    roi_kernel<<<BDIM * NBOX, CCH>>>(bboxes);

    dense_kernel<<<(BDIM * NBOX) / 2, 256, DSMEM_BYTES>>>(dense_w, dense_b, out);
}

// round 14
// speedup vs baseline: 1.5044x; 1.5044x over previous
#include <cuda_runtime.h>
#include <cuda_fp16.h>
#include <cstdint>

// ---------------------------------------------------------------------------
// Problem constants
// ---------------------------------------------------------------------------
#define BDIM   16
#define FH     32
#define FW     32
#define NBOX   16
#define CCH    256     // conv out channels
#define DDIM   256     // dense out
#define KDIM   768     // 16*16*3
#define M_TOT  16384   // B*32*32
#define S_ROI  7

// Scratch (static __device__ — no allocations allowed)
__device__ __half g_Wh[CCH * KDIM];          // W transposed+f16: [256 n][768 k]
__device__ __half g_feat[M_TOT * CCH];       // conv+relu feat [16384, 256] f16
__device__ float  g_obj[BDIM * NBOX * CCH];  // pooled rois   [256, 256]

// ---------------------------------------------------------------------------
// helpers
// ---------------------------------------------------------------------------
__device__ __forceinline__ uint32_t smem_to_u32(const void* smem_ptr) {
    uint32_t addr;
    asm("{ .reg .u64 tmp; cvta.to.shared.u64 tmp, %1; cvt.u32.u64 %0, tmp; }"
        : "=r"(addr) : "l"(smem_ptr));
    return addr;
}
__device__ __forceinline__ uint32_t f2h2(float lo, float hi) {
    uint32_t r;
    asm("cvt.rn.f16x2.f32 %0, %1, %2;" : "=r"(r) : "f"(hi), "f"(lo));
    return r;
}
__device__ __forceinline__ void mma_f16(float* d, const uint32_t* a, const uint32_t* b) {
    asm volatile(
        "mma.sync.aligned.m16n8k16.row.col.f32.f16.f16.f32 "
        "{%0,%1,%2,%3}, {%4,%5,%6,%7}, {%8,%9}, {%0,%1,%2,%3};"
        : "+f"(d[0]), "+f"(d[1]), "+f"(d[2]), "+f"(d[3])
        : "r"(a[0]), "r"(a[1]), "r"(a[2]), "r"(a[3]), "r"(b[0]), "r"(b[1]));
}
__device__ __forceinline__ void cp16(uint32_t smem_dst, const void* gsrc) {
    asm volatile("cp.async.cg.shared.global [%0], [%1], 16;"
                 :: "r"(smem_dst), "l"(gsrc));
}
#define CP_COMMIT() asm volatile("cp.async.commit_group;" ::: "memory")
#define CP_WAIT1()  asm volatile("cp.async.wait_group 1;"  ::: "memory")
#define CP_WAIT0()  asm volatile("cp.async.wait_group 0;"  ::: "memory")

// ---------------------------------------------------------------------------
// 0) W prepass: W[768,256] f32 -> g_Wh[256 n][768 k] f16 (transpose+convert)
// ---------------------------------------------------------------------------
__global__ __launch_bounds__(256) void wprep_kernel(const float* __restrict__ W) {
    __shared__ float t[32][33];
    int kb = blockIdx.x * 32, nb = blockIdx.y * 32;
    int tx = threadIdx.x & 31, ty = threadIdx.x >> 5;   // 32 x 8
    #pragma unroll
    for (int i = 0; i < 32; i += 8)
        t[ty + i][tx] = W[(kb + ty + i) * CCH + nb + tx];
    __syncthreads();
    #pragma unroll
    for (int i = 0; i < 32; i += 8)
        g_Wh[(nb + ty + i) * KDIM + kb + tx] = __float2half_rn(t[tx][ty + i]);
}

// ---------------------------------------------------------------------------
// 1) Conv-as-GEMM, fused im2col, fp16 m16n8k16 mma, 3-stage cp.async,
//    single barrier per chunk. CTA tile 128x128, 8 warps each 64x32.
//    (round-12 proven version)
// ---------------------------------------------------------------------------
#define BK      32
#define NCH     (KDIM / BK)          // 24
#define LDA     40                   // floats per A row (32 data + 8 pad)
#define LDBT    40                   // halves per B row (32 data + 8 pad)
#define A_BYTES (128 * LDA * 4)      // 20480
#define B_BYTES (128 * LDBT * 2)     // 10240
#define STG_BYTES (A_BYTES + B_BYTES)// 30720
#define STAGES  3
#define SMEM_BYTES (STAGES * STG_BYTES)   // 92160

__global__ __launch_bounds__(256, 2) void conv_mma_kernel(
    const float* __restrict__ img,     // [16,512,512,3]
    const float* __restrict__ bias)    // [256]
{
    extern __shared__ float smem[];
    const uint32_t sb = smem_to_u32(smem);

    const int tid = threadIdx.x;
    const int wid = tid >> 5;
    const int lid = tid & 31;
    const int g   = lid >> 2;          // 0..7
    const int t4  = lid & 3;           // 0..3
    const int wm  = wid & 1;           // 2 warps in M
    const int wn  = wid >> 1;          // 4 warps in N

    const int n0 = blockIdx.x * 128;
    const int m0 = blockIdx.y * 128;

    // cp.async source bases
    const float* aBase[4];
    #pragma unroll
    for (int i = 0; i < 4; i++) {
        int f4  = tid + i * 256;               // 0..1023
        int row = f4 >> 3;                     // 0..127
        int m   = m0 + row;
        int b   = m >> 10;
        int oy  = (m >> 5) & 31;
        int ox  = m & 31;
        aBase[i] = img + (size_t)((b * 512 + oy * 16) * 512 + ox * 16) * 3;
    }
    const __half* bBase[2];
    #pragma unroll
    for (int i = 0; i < 2; i++) {
        int f4  = tid + i * 256;               // 0..511
        int row = f4 >> 2;                     // 0..127
        int q   = f4 & 3;
        bBase[i] = g_Wh + (size_t)(n0 + row) * KDIM + q * 8;
    }

    auto issue = [&](int c) {
        const int k0 = c * BK;
        const uint32_t soff = sb + (uint32_t)(c % STAGES) * STG_BYTES;
        #pragma unroll
        for (int i = 0; i < 4; i++) {
            int f4  = tid + i * 256;
            int row = f4 >> 3;
            int q   = f4 & 7;
            int k   = k0 + q * 4;
            int ky  = k / 48;
            int rem = k - ky * 48;             // 4 | 48 -> never crosses pixel run
            cp16(soff + (uint32_t)(row * (LDA * 4) + q * 16),
                 aBase[i] + ky * 1536 + rem);
        }
        #pragma unroll
        for (int i = 0; i < 2; i++) {
            int f4  = tid + i * 256;
            int row = f4 >> 2;
            int q   = f4 & 3;
            cp16(soff + (uint32_t)(A_BYTES + row * (LDBT * 2) + q * 16),
                 bBase[i] + k0);
        }
        CP_COMMIT();
    };

    float acc[4][4][4];
    #pragma unroll
    for (int i = 0; i < 4; i++)
        #pragma unroll
        for (int j = 0; j < 4; j++)
            #pragma unroll
            for (int r = 0; r < 4; r++) acc[i][j][r] = 0.f;

    // prologue: 2 chunks in flight
    issue(0); issue(1);

    for (int c = 0; c < NCH; c++) {
        if (c + 1 < NCH) CP_WAIT1(); else CP_WAIT0();
        __syncthreads();                       // frees stage (c+2)%3, chunk c visible
        if (c + 2 < NCH) issue(c + 2);

        const float*    As  = smem + (c % STAGES) * (STG_BYTES / 4);
        const uint32_t* Bsu = (const uint32_t*)((const char*)As + A_BYTES);

        #pragma unroll
        for (int kk = 0; kk < 2; kk++) {       // two k16 steps per chunk
            const int ka = kk * 16 + 2 * t4;   // A k offset (floats)
            uint32_t afr[4][4], bfr[4][2];
            #pragma unroll
            for (int mi = 0; mi < 4; mi++) {
                int mr = wm * 64 + mi * 16 + g;
                float2 v0 = *(const float2*)&As[mr * LDA + ka];
                float2 v1 = *(const float2*)&As[(mr + 8) * LDA + ka];
                float2 v2 = *(const float2*)&As[mr * LDA + ka + 8];
                float2 v3 = *(const float2*)&As[(mr + 8) * LDA + ka + 8];
                afr[mi][0] = f2h2(v0.x, v0.y);
                afr[mi][1] = f2h2(v1.x, v1.y);
                afr[mi][2] = f2h2(v2.x, v2.y);
                afr[mi][3] = f2h2(v3.x, v3.y);
            }
            #pragma unroll
            for (int ni = 0; ni < 4; ni++) {
                int nc = wn * 32 + ni * 8 + g;
                bfr[ni][0] = Bsu[nc * (LDBT / 2) + kk * 8 + t4];
                bfr[ni][1] = Bsu[nc * (LDBT / 2) + kk * 8 + t4 + 4];
            }
            #pragma unroll
            for (int mi = 0; mi < 4; mi++)
                #pragma unroll
                for (int ni = 0; ni < 4; ni++)
                    mma_f16(acc[mi][ni], afr[mi], bfr[ni]);
        }
    }

    // epilogue: bias + relu -> g_feat (f16)
    #pragma unroll
    for (int mi = 0; mi < 4; mi++) {
        #pragma unroll
        for (int ni = 0; ni < 4; ni++) {
            int m = m0 + wm * 64 + mi * 16 + g;
            int n = n0 + wn * 32 + ni * 8 + 2 * t4;
            float b0 = bias[n], b1 = bias[n + 1];
            __half2 h0 = __floats2half2_rn(fmaxf(acc[mi][ni][0] + b0, 0.f),
                                           fmaxf(acc[mi][ni][1] + b1, 0.f));
            __half2 h1 = __floats2half2_rn(fmaxf(acc[mi][ni][2] + b0, 0.f),
                                           fmaxf(acc[mi][ni][3] + b1, 0.f));
            *(__half2*)&g_feat[(size_t)m * CCH + n]       = h0;
            *(__half2*)&g_feat[(size_t)(m + 8) * CCH + n] = h1;
        }
    }
}

// ---------------------------------------------------------------------------
// 2) ROI align (bilinear, 7x7) + mean + notrack mask — MLP-wide rewrite.
//    Block = roi (256 blocks, 8 warps). Warp w handles samples {w, w+8, ...}
//    (<=7 serial samples). Lane covers 8 channels via one uint4 (16B) per
//    corner -> 4-way MLP per sample, ~25 wide loads per thread instead of
//    196 narrow serial ones. Cross-warp reduce via SMEM.
// ---------------------------------------------------------------------------
__global__ __launch_bounds__(256) void roi_kernel(const float* __restrict__ boxes) {
    __shared__ float sPart[8][CCH];            // 8KB partials
    const int roi  = blockIdx.x;
    const int b    = roi >> 4;
    const int tid  = threadIdx.x;
    const int w    = tid >> 5;
    const int lane = tid & 31;

    float4 box = *(const float4*)&boxes[roi * 4];
    float ymin = box.x, xmin = box.y, ymax = box.z, xmax = box.w;
    bool empty = (ymin == -1.f) && (xmin == -1.f) && (ymax == -1.f) && (xmax == -1.f);
    if (empty) { g_obj[(size_t)roi * CCH + tid] = 0.f; return; }

    const __half* fb = g_feat + (size_t)b * FH * FW * CCH;
    const int coff = lane * 8;                 // 8 channels per lane

    float accv[8];
    #pragma unroll
    for (int q = 0; q < 8; q++) accv[q] = 0.f;

    for (int s = w; s < S_ROI * S_ROI; s += 8) {
        int i = s / S_ROI;                     // y sample
        int j = s - i * S_ROI;                 // x sample
        float stepy = ((float)i + 0.5f) / (float)S_ROI;
        float stepx = ((float)j + 0.5f) / (float)S_ROI;
        float py = (ymin + (ymax - ymin) * stepy) * (float)FH - 0.5f;
        float px = (xmin + (xmax - xmin) * stepx) * (float)FW - 0.5f;
        float y0f = floorf(py), x0f = floorf(px);
        float wy = py - y0f, wx = px - x0f;
        int yi = (int)y0f, xi = (int)x0f;
        int y0 = min(max(yi, 0), FH - 1);
        int y1 = min(max(yi + 1, 0), FH - 1);
        int x0 = min(max(xi, 0), FW - 1);
        int x1 = min(max(xi + 1, 0), FW - 1);

        // 4 independent 16B loads (8 halves each)
        uint4 f00 = *(const uint4*)(fb + (y0 * FW + x0) * CCH + coff);
        uint4 f01 = *(const uint4*)(fb + (y0 * FW + x1) * CCH + coff);
        uint4 f10 = *(const uint4*)(fb + (y1 * FW + x0) * CCH + coff);
        uint4 f11 = *(const uint4*)(fb + (y1 * FW + x1) * CCH + coff);

        float w00 = (1.f - wy) * (1.f - wx);
        float w01 = (1.f - wy) * wx;
        float w10 = wy * (1.f - wx);
        float w11 = wy * wx;

        const __half2* h00 = (const __half2*)&f00;
        const __half2* h01 = (const __half2*)&f01;
        const __half2* h10 = (const __half2*)&f10;
        const __half2* h11 = (const __half2*)&f11;
        #pragma unroll
        for (int q = 0; q < 4; q++) {
            float2 a = __half22float2(h00[q]);
            float2 c = __half22float2(h01[q]);
            float2 d = __half22float2(h10[q]);
            float2 e = __half22float2(h11[q]);
            accv[2 * q]     += w00 * a.x + w01 * c.x + w10 * d.x + w11 * e.x;
            accv[2 * q + 1] += w00 * a.y + w01 * c.y + w10 * d.y + w11 * e.y;
        }
    }

    // per-warp partials -> SMEM (two float4 stores, conflict-light)
    *(float4*)&sPart[w][coff]     = *(float4*)&accv[0];
    *(float4*)&sPart[w][coff + 4] = *(float4*)&accv[4];
    __syncthreads();

    // channel tid: sum 8 warp partials
    float tot = 0.f;
    #pragma unroll
    for (int ww = 0; ww < 8; ww++) tot += sPart[ww][tid];
    g_obj[(size_t)roi * CCH + tid] = tot * (1.f / (S_ROI * S_ROI));
}

// ---------------------------------------------------------------------------
// 3) Dense: out[256,256] = obj[256,256] @ Wd[256,256] + bd.
//    128 blocks x 2 rows, Wd via 3-stage cp.async pipeline.
// ---------------------------------------------------------------------------
#define DK        32                          // k-rows per stage
#define DNSTG     (CCH / DK)                  // 8 stages
#define DSTG_FLT  (DK * DDIM)                 // 8192 floats / stage
#define DSMEM_BYTES ((3 * DSTG_FLT + 2 * CCH) * 4)   // 100352

__global__ __launch_bounds__(256) void dense_kernel(
    const float* __restrict__ Wd, const float* __restrict__ bd,
    float* __restrict__ out)
{
    extern __shared__ float s[];
    float* sW   = s;                          // [3][DK*DDIM]
    float* sObj = s + 3 * DSTG_FLT;           // [2][CCH]
    const uint32_t sb = smem_to_u32(s);

    const int tid = threadIdx.x;
    const int r0  = blockIdx.x * 2;

    auto issueW = [&](int st) {
        const uint32_t soff = sb + (uint32_t)(st % 3) * (DSTG_FLT * 4);
        const int k0 = st * DK;
        #pragma unroll
        for (int i = 0; i < 8; i++) {
            int f4  = tid + i * 256;           // 0..2047
            int row = f4 >> 6;                 // 0..31
            int q   = f4 & 63;
            cp16(soff + (uint32_t)(row * DDIM + q * 4) * 4,
                 Wd + (size_t)(k0 + row) * DDIM + q * 4);
        }
        CP_COMMIT();
    };

    issueW(0); issueW(1);

    sObj[tid]       = g_obj[(size_t)r0 * CCH + tid];
    sObj[CCH + tid] = g_obj[(size_t)(r0 + 1) * CCH + tid];
    const float bb = bd[tid];
    __syncthreads();

    float acc0 = 0.f, acc1 = 0.f;
    for (int st = 0; st < DNSTG; st++) {
        if (st + 1 < DNSTG) CP_WAIT1(); else CP_WAIT0();
        __syncthreads();
        if (st + 2 < DNSTG) issueW(st + 2);

        const float* w = sW + (st % 3) * DSTG_FLT;
        const int k0 = st * DK;
        #pragma unroll
        for (int k = 0; k < DK; k++) {
            float wv = w[k * DDIM + tid];
            acc0 += sObj[k0 + k] * wv;
            acc1 += sObj[CCH + k0 + k] * wv;
        }
    }

    out[(size_t)r0 * DDIM + tid]       = acc0 + bb;
    out[(size_t)(r0 + 1) * DDIM + tid] = acc1 + bb;
}

// ---------------------------------------------------------------------------
// Launch
// ---------------------------------------------------------------------------
extern "C" void kernel_launch(void* const* d_in, const int* in_sizes, int n_in,
                              void* d_out, int out_size) {
    const float* images  = (const float*)d_in[0];
    const float* bboxes  = (const float*)d_in[1];
    const float* conv_w  = (const float*)d_in[2];
    const float* conv_b  = (const float*)d_in[3];
    const float* dense_w = (const float*)d_in[4];
    const float* dense_b = (const float*)d_in[5];
    float* out = (float*)d_out;

    static bool attr_set = false;
    if (!attr_set) {
        cudaFuncSetAttribute(conv_mma_kernel,
                             cudaFuncAttributeMaxDynamicSharedMemorySize, SMEM_BYTES);
        cudaFuncSetAttribute(dense_kernel,
                             cudaFuncAttributeMaxDynamicSharedMemorySize, DSMEM_BYTES);
        attr_set = true;
    }

    dim3 wgrid(KDIM / 32, CCH / 32);     // (24, 8)
    wprep_kernel<<<wgrid, 256>>>(conv_w);

    dim3 grid(CCH / 128, M_TOT / 128);   // (2, 128)
    conv_mma_kernel<<<grid, 256, SMEM_BYTES>>>(images, conv_b);

    roi_kernel<<<BDIM * NBOX, CCH>>>(bboxes);

    dense_kernel<<<(BDIM * NBOX) / 2, 256, DSMEM_BYTES>>>(dense_w, dense_b, out);
}

// round 15
// speedup vs baseline: 1.5369x; 1.0216x over previous
#include <cuda_runtime.h>
#include <cuda_fp16.h>
#include <cstdint>

// ---------------------------------------------------------------------------
// Problem constants
// ---------------------------------------------------------------------------
#define BDIM   16
#define FH     32
#define FW     32
#define NBOX   16
#define CCH    256     // conv out channels
#define DDIM   256     // dense out
#define KDIM   768     // 16*16*3
#define M_TOT  16384   // B*32*32
#define S_ROI  7

// Scratch (static __device__ — no allocations allowed)
__device__ __half g_Wh[CCH * KDIM];          // W transposed+f16: [256 n][768 k]
__device__ __half g_feat[M_TOT * CCH];       // conv+relu feat [16384, 256] f16
__device__ float  g_obj[BDIM * NBOX * CCH];  // pooled rois   [256, 256]

// ---------------------------------------------------------------------------
// helpers
// ---------------------------------------------------------------------------
__device__ __forceinline__ uint32_t smem_to_u32(const void* smem_ptr) {
    uint32_t addr;
    asm("{ .reg .u64 tmp; cvta.to.shared.u64 tmp, %1; cvt.u32.u64 %0, tmp; }"
        : "=r"(addr) : "l"(smem_ptr));
    return addr;
}
__device__ __forceinline__ uint32_t f2h2(float lo, float hi) {
    uint32_t r;
    asm("cvt.rn.f16x2.f32 %0, %1, %2;" : "=r"(r) : "f"(hi), "f"(lo));
    return r;
}
__device__ __forceinline__ void mma_f16(float* d, const uint32_t* a, const uint32_t* b) {
    asm volatile(
        "mma.sync.aligned.m16n8k16.row.col.f32.f16.f16.f32 "
        "{%0,%1,%2,%3}, {%4,%5,%6,%7}, {%8,%9}, {%0,%1,%2,%3};"
        : "+f"(d[0]), "+f"(d[1]), "+f"(d[2]), "+f"(d[3])
        : "r"(a[0]), "r"(a[1]), "r"(a[2]), "r"(a[3]), "r"(b[0]), "r"(b[1]));
}
__device__ __forceinline__ void cp16(uint32_t smem_dst, const void* gsrc) {
    asm volatile("cp.async.cg.shared.global [%0], [%1], 16;"
                 :: "r"(smem_dst), "l"(gsrc));
}
#define CP_COMMIT() asm volatile("cp.async.commit_group;" ::: "memory")
#define CP_WAIT1()  asm volatile("cp.async.wait_group 1;"  ::: "memory")
#define CP_WAIT0()  asm volatile("cp.async.wait_group 0;"  ::: "memory")

// ---------------------------------------------------------------------------
// 0) W prepass: W[768,256] f32 -> g_Wh[256 n][768 k] f16 (transpose+convert)
// ---------------------------------------------------------------------------
__global__ __launch_bounds__(256) void wprep_kernel(const float* __restrict__ W) {
    __shared__ float t[32][33];
    int kb = blockIdx.x * 32, nb = blockIdx.y * 32;
    int tx = threadIdx.x & 31, ty = threadIdx.x >> 5;   // 32 x 8
    #pragma unroll
    for (int i = 0; i < 32; i += 8)
        t[ty + i][tx] = W[(kb + ty + i) * CCH + nb + tx];
    __syncthreads();
    #pragma unroll
    for (int i = 0; i < 32; i += 8)
        g_Wh[(nb + ty + i) * KDIM + kb + tx] = __float2half_rn(t[tx][ty + i]);
    cudaTriggerProgrammaticLaunchCompletion();
}

// ---------------------------------------------------------------------------
// 1) Conv-as-GEMM, fused im2col, fp16 m16n8k16 mma, 3-stage cp.async,
//    single barrier per chunk. CTA tile 128x128, 8 warps each 64x32.
// ---------------------------------------------------------------------------
#define BK      32
#define NCH     (KDIM / BK)          // 24
#define LDA     40                   // floats per A row (32 data + 8 pad)
#define LDBT    40                   // halves per B row (32 data + 8 pad)
#define A_BYTES (128 * LDA * 4)      // 20480
#define B_BYTES (128 * LDBT * 2)     // 10240
#define STG_BYTES (A_BYTES + B_BYTES)// 30720
#define STAGES  3
#define SMEM_BYTES (STAGES * STG_BYTES)   // 92160

__global__ __launch_bounds__(256, 2) void conv_mma_kernel(
    const float* __restrict__ img,     // [16,512,512,3]
    const float* __restrict__ bias)    // [256]
{
    extern __shared__ float smem[];
    const uint32_t sb = smem_to_u32(smem);

    const int tid = threadIdx.x;
    const int wid = tid >> 5;
    const int lid = tid & 31;
    const int g   = lid >> 2;          // 0..7
    const int t4  = lid & 3;           // 0..3
    const int wm  = wid & 1;           // 2 warps in M
    const int wn  = wid >> 1;          // 4 warps in N

    const int n0 = blockIdx.x * 128;
    const int m0 = blockIdx.y * 128;

    // cp.async source bases (independent prologue math)
    const float* aBase[4];
    #pragma unroll
    for (int i = 0; i < 4; i++) {
        int f4  = tid + i * 256;               // 0..1023
        int row = f4 >> 3;                     // 0..127
        int m   = m0 + row;
        int b   = m >> 10;
        int oy  = (m >> 5) & 31;
        int ox  = m & 31;
        aBase[i] = img + (size_t)((b * 512 + oy * 16) * 512 + ox * 16) * 3;
    }
    const __half* bBase[2];
    #pragma unroll
    for (int i = 0; i < 2; i++) {
        int f4  = tid + i * 256;               // 0..511
        int row = f4 >> 2;                     // 0..127
        int q   = f4 & 3;
        bBase[i] = g_Wh + (size_t)(n0 + row) * KDIM + q * 8;
    }

    auto issue = [&](int c) {
        const int k0 = c * BK;
        const uint32_t soff = sb + (uint32_t)(c % STAGES) * STG_BYTES;
        #pragma unroll
        for (int i = 0; i < 4; i++) {
            int f4  = tid + i * 256;
            int row = f4 >> 3;
            int q   = f4 & 7;
            int k   = k0 + q * 4;
            int ky  = k / 48;
            int rem = k - ky * 48;             // 4 | 48 -> never crosses pixel run
            cp16(soff + (uint32_t)(row * (LDA * 4) + q * 16),
                 aBase[i] + ky * 1536 + rem);
        }
        #pragma unroll
        for (int i = 0; i < 2; i++) {
            int f4  = tid + i * 256;
            int row = f4 >> 2;
            int q   = f4 & 3;
            cp16(soff + (uint32_t)(A_BYTES + row * (LDBT * 2) + q * 16),
                 bBase[i] + k0);
        }
        CP_COMMIT();
    };

    float acc[4][4][4];
    #pragma unroll
    for (int i = 0; i < 4; i++)
        #pragma unroll
        for (int j = 0; j < 4; j++)
            #pragma unroll
            for (int r = 0; r < 4; r++) acc[i][j][r] = 0.f;

    // wait for wprep's g_Wh before the first B load
    cudaGridDependencySynchronize();

    // prologue: 2 chunks in flight
    issue(0); issue(1);

    for (int c = 0; c < NCH; c++) {
        if (c + 1 < NCH) CP_WAIT1(); else CP_WAIT0();
        __syncthreads();                       // frees stage (c+2)%3, chunk c visible
        if (c + 2 < NCH) issue(c + 2);

        const float*    As  = smem + (c % STAGES) * (STG_BYTES / 4);
        const uint32_t* Bsu = (const uint32_t*)((const char*)As + A_BYTES);

        #pragma unroll
        for (int kk = 0; kk < 2; kk++) {       // two k16 steps per chunk
            const int ka = kk * 16 + 2 * t4;   // A k offset (floats)
            uint32_t afr[4][4], bfr[4][2];
            #pragma unroll
            for (int mi = 0; mi < 4; mi++) {
                int mr = wm * 64 + mi * 16 + g;
                float2 v0 = *(const float2*)&As[mr * LDA + ka];
                float2 v1 = *(const float2*)&As[(mr + 8) * LDA + ka];
                float2 v2 = *(const float2*)&As[mr * LDA + ka + 8];
                float2 v3 = *(const float2*)&As[(mr + 8) * LDA + ka + 8];
                afr[mi][0] = f2h2(v0.x, v0.y);
                afr[mi][1] = f2h2(v1.x, v1.y);
                afr[mi][2] = f2h2(v2.x, v2.y);
                afr[mi][3] = f2h2(v3.x, v3.y);
            }
            #pragma unroll
            for (int ni = 0; ni < 4; ni++) {
                int nc = wn * 32 + ni * 8 + g;
                bfr[ni][0] = Bsu[nc * (LDBT / 2) + kk * 8 + t4];
                bfr[ni][1] = Bsu[nc * (LDBT / 2) + kk * 8 + t4 + 4];
            }
            #pragma unroll
            for (int mi = 0; mi < 4; mi++)
                #pragma unroll
                for (int ni = 0; ni < 4; ni++)
                    mma_f16(acc[mi][ni], afr[mi], bfr[ni]);
        }
    }

    // epilogue: bias + relu -> g_feat (f16)
    #pragma unroll
    for (int mi = 0; mi < 4; mi++) {
        #pragma unroll
        for (int ni = 0; ni < 4; ni++) {
            int m = m0 + wm * 64 + mi * 16 + g;
            int n = n0 + wn * 32 + ni * 8 + 2 * t4;
            float b0 = bias[n], b1 = bias[n + 1];
            __half2 h0 = __floats2half2_rn(fmaxf(acc[mi][ni][0] + b0, 0.f),
                                           fmaxf(acc[mi][ni][1] + b1, 0.f));
            __half2 h1 = __floats2half2_rn(fmaxf(acc[mi][ni][2] + b0, 0.f),
                                           fmaxf(acc[mi][ni][3] + b1, 0.f));
            *(__half2*)&g_feat[(size_t)m * CCH + n]       = h0;
            *(__half2*)&g_feat[(size_t)(m + 8) * CCH + n] = h1;
        }
    }
    cudaTriggerProgrammaticLaunchCompletion();
}

// ---------------------------------------------------------------------------
// 2) ROI align (bilinear, 7x7) + mean + notrack mask — MLP-wide version.
// ---------------------------------------------------------------------------
__global__ __launch_bounds__(256) void roi_kernel(const float* __restrict__ boxes) {
    __shared__ float sPart[8][CCH];            // 8KB partials
    const int roi  = blockIdx.x;
    const int b    = roi >> 4;
    const int tid  = threadIdx.x;
    const int w    = tid >> 5;
    const int lane = tid & 31;

    float4 box = *(const float4*)&boxes[roi * 4];
    float ymin = box.x, xmin = box.y, ymax = box.z, xmax = box.w;
    bool empty = (ymin == -1.f) && (xmin == -1.f) && (ymax == -1.f) && (xmax == -1.f);
    if (empty) {
        g_obj[(size_t)roi * CCH + tid] = 0.f;
        cudaTriggerProgrammaticLaunchCompletion();
        return;
    }

    const __half* fb = g_feat + (size_t)b * FH * FW * CCH;
    const int coff = lane * 8;                 // 8 channels per lane

    float accv[8];
    #pragma unroll
    for (int q = 0; q < 8; q++) accv[q] = 0.f;

    // wait for conv's g_feat before the first gather
    cudaGridDependencySynchronize();

    for (int s = w; s < S_ROI * S_ROI; s += 8) {
        int i = s / S_ROI;                     // y sample
        int j = s - i * S_ROI;                 // x sample
        float stepy = ((float)i + 0.5f) / (float)S_ROI;
        float stepx = ((float)j + 0.5f) / (float)S_ROI;
        float py = (ymin + (ymax - ymin) * stepy) * (float)FH - 0.5f;
        float px = (xmin + (xmax - xmin) * stepx) * (float)FW - 0.5f;
        float y0f = floorf(py), x0f = floorf(px);
        float wy = py - y0f, wx = px - x0f;
        int yi = (int)y0f, xi = (int)x0f;
        int y0 = min(max(yi, 0), FH - 1);
        int y1 = min(max(yi + 1, 0), FH - 1);
        int x0 = min(max(xi, 0), FW - 1);
        int x1 = min(max(xi + 1, 0), FW - 1);

        uint4 f00 = *(const uint4*)(fb + (y0 * FW + x0) * CCH + coff);
        uint4 f01 = *(const uint4*)(fb + (y0 * FW + x1) * CCH + coff);
        uint4 f10 = *(const uint4*)(fb + (y1 * FW + x0) * CCH + coff);
        uint4 f11 = *(const uint4*)(fb + (y1 * FW + x1) * CCH + coff);

        float w00 = (1.f - wy) * (1.f - wx);
        float w01 = (1.f - wy) * wx;
        float w10 = wy * (1.f - wx);
        float w11 = wy * wx;

        const __half2* h00 = (const __half2*)&f00;
        const __half2* h01 = (const __half2*)&f01;
        const __half2* h10 = (const __half2*)&f10;
        const __half2* h11 = (const __half2*)&f11;
        #pragma unroll
        for (int q = 0; q < 4; q++) {
            float2 a = __half22float2(h00[q]);
            float2 c = __half22float2(h01[q]);
            float2 d = __half22float2(h10[q]);
            float2 e = __half22float2(h11[q]);
            accv[2 * q]     += w00 * a.x + w01 * c.x + w10 * d.x + w11 * e.x;
            accv[2 * q + 1] += w00 * a.y + w01 * c.y + w10 * d.y + w11 * e.y;
        }
    }

    *(float4*)&sPart[w][coff]     = *(float4*)&accv[0];
    *(float4*)&sPart[w][coff + 4] = *(float4*)&accv[4];
    __syncthreads();

    float tot = 0.f;
    #pragma unroll
    for (int ww = 0; ww < 8; ww++) tot += sPart[ww][tid];
    g_obj[(size_t)roi * CCH + tid] = tot * (1.f / (S_ROI * S_ROI));
    cudaTriggerProgrammaticLaunchCompletion();
}

// ---------------------------------------------------------------------------
// 3) Dense: out[256,256] = obj[256,256] @ Wd[256,256] + bd.
//    128 blocks x 2 rows, Wd via 3-stage cp.async pipeline, DK=64
//    (4 waits instead of 8). First two stages prefetch BEFORE the PDL
//    dependency sync — hidden under roi's tail.
// ---------------------------------------------------------------------------
#define DK        64                          // k-rows per stage
#define DNSTG     (CCH / DK)                  // 4 stages
#define DSTG_FLT  (DK * DDIM)                 // 16384 floats / stage
#define DSMEM_BYTES ((3 * DSTG_FLT + 2 * CCH) * 4)   // 198656

__global__ __launch_bounds__(256) void dense_kernel(
    const float* __restrict__ Wd, const float* __restrict__ bd,
    float* __restrict__ out)
{
    extern __shared__ float s[];
    float* sW   = s;                          // [3][DK*DDIM]
    float* sObj = s + 3 * DSTG_FLT;           // [2][CCH]
    const uint32_t sb = smem_to_u32(s);

    const int tid = threadIdx.x;
    const int r0  = blockIdx.x * 2;

    auto issueW = [&](int st) {
        const uint32_t soff = sb + (uint32_t)(st % 3) * (DSTG_FLT * 4);
        const int k0 = st * DK;
        #pragma unroll
        for (int i = 0; i < 16; i++) {
            int f4  = tid + i * 256;           // 0..4095
            int row = f4 >> 6;                 // 0..63
            int q   = f4 & 63;
            cp16(soff + (uint32_t)(row * DDIM + q * 4) * 4,
                 Wd + (size_t)(k0 + row) * DDIM + q * 4);
        }
        CP_COMMIT();
    };

    // Wd and bd are kernel inputs — independent of roi; prefetch early.
    issueW(0); issueW(1);
    const float bb = bd[tid];

    // wait for roi's g_obj
    cudaGridDependencySynchronize();

    sObj[tid]       = g_obj[(size_t)r0 * CCH + tid];
    sObj[CCH + tid] = g_obj[(size_t)(r0 + 1) * CCH + tid];
    __syncthreads();

    float acc0 = 0.f, acc1 = 0.f;
    for (int st = 0; st < DNSTG; st++) {
        if (st + 1 < DNSTG) CP_WAIT1(); else CP_WAIT0();
        __syncthreads();
        if (st + 2 < DNSTG) issueW(st + 2);

        const float* w = sW + (st % 3) * DSTG_FLT;
        const int k0 = st * DK;
        #pragma unroll
        for (int k = 0; k < DK; k++) {
            float wv = w[k * DDIM + tid];
            acc0 += sObj[k0 + k] * wv;
            acc1 += sObj[CCH + k0 + k] * wv;
        }
    }

    out[(size_t)r0 * DDIM + tid]       = acc0 + bb;
    out[(size_t)(r0 + 1) * DDIM + tid] = acc1 + bb;
}

// ---------------------------------------------------------------------------
// Launch — PDL chain: wprep -> conv -> roi -> dense
// ---------------------------------------------------------------------------
static void launch_pdl(const void* fn, dim3 grid, dim3 block, size_t smem,
                       void** args) {
    cudaLaunchConfig_t cfg = {};
    cfg.gridDim = grid;
    cfg.blockDim = block;
    cfg.dynamicSmemBytes = smem;
    cfg.stream = 0;
    cudaLaunchAttribute attr[1];
    attr[0].id = cudaLaunchAttributeProgrammaticStreamSerialization;
    attr[0].val.programmaticStreamSerializationAllowed = 1;
    cfg.attrs = attr;
    cfg.numAttrs = 1;
    cudaLaunchKernelExC(&cfg, fn, args);
}

extern "C" void kernel_launch(void* const* d_in, const int* in_sizes, int n_in,
                              void* d_out, int out_size) {
    const float* images  = (const float*)d_in[0];
    const float* bboxes  = (const float*)d_in[1];
    const float* conv_w  = (const float*)d_in[2];
    const float* conv_b  = (const float*)d_in[3];
    const float* dense_w = (const float*)d_in[4];
    const float* dense_b = (const float*)d_in[5];
    float* out = (float*)d_out;

    static bool attr_set = false;
    if (!attr_set) {
        cudaFuncSetAttribute(conv_mma_kernel,
                             cudaFuncAttributeMaxDynamicSharedMemorySize, SMEM_BYTES);
        cudaFuncSetAttribute(dense_kernel,
                             cudaFuncAttributeMaxDynamicSharedMemorySize, DSMEM_BYTES);
        attr_set = true;
    }

    dim3 wgrid(KDIM / 32, CCH / 32);     // (24, 8)
    wprep_kernel<<<wgrid, 256>>>(conv_w);

    {
        void* args[] = {(void*)&images, (void*)&conv_b};
        launch_pdl((const void*)conv_mma_kernel,
                   dim3(CCH / 128, M_TOT / 128), dim3(256), SMEM_BYTES, args);
    }
    {
        void* args[] = {(void*)&bboxes};
        launch_pdl((const void*)roi_kernel,
                   dim3(BDIM * NBOX), dim3(256), 0, args);
    }
    {
        void* args[] = {(void*)&dense_w, (void*)&dense_b, (void*)&out};
        launch_pdl((const void*)dense_kernel,
                   dim3((BDIM * NBOX) / 2), dim3(256), DSMEM_BYTES, args);
    }
}

// round 16
// speedup vs baseline: 1.5984x; 1.0400x over previous
#include <cuda_runtime.h>
#include <cuda_fp16.h>
#include <cstdint>

// ---------------------------------------------------------------------------
// Problem constants
// ---------------------------------------------------------------------------
#define BDIM   16
#define FH     32
#define FW     32
#define NBOX   16
#define CCH    256     // conv out channels
#define DDIM   256     // dense out
#define KDIM   768     // 16*16*3
#define M_TOT  16384   // B*32*32
#define S_ROI  7

// Scratch (static __device__ — no allocations allowed)
__device__ __half g_Wh[CCH * KDIM];          // W transposed+f16: [256 n][768 k]
__device__ __half g_feat[M_TOT * CCH];       // conv+relu feat [16384, 256] f16
__device__ float  g_obj[BDIM * NBOX * CCH];  // pooled rois   [256, 256]

// ---------------------------------------------------------------------------
// helpers
// ---------------------------------------------------------------------------
__device__ __forceinline__ uint32_t smem_to_u32(const void* smem_ptr) {
    uint32_t addr;
    asm("{ .reg .u64 tmp; cvta.to.shared.u64 tmp, %1; cvt.u32.u64 %0, tmp; }"
        : "=r"(addr) : "l"(smem_ptr));
    return addr;
}
__device__ __forceinline__ uint32_t f2h2(float lo, float hi) {
    uint32_t r;
    asm("cvt.rn.f16x2.f32 %0, %1, %2;" : "=r"(r) : "f"(hi), "f"(lo));
    return r;
}
__device__ __forceinline__ void mma_f16(float* d, const uint32_t* a, const uint32_t* b) {
    asm volatile(
        "mma.sync.aligned.m16n8k16.row.col.f32.f16.f16.f32 "
        "{%0,%1,%2,%3}, {%4,%5,%6,%7}, {%8,%9}, {%0,%1,%2,%3};"
        : "+f"(d[0]), "+f"(d[1]), "+f"(d[2]), "+f"(d[3])
        : "r"(a[0]), "r"(a[1]), "r"(a[2]), "r"(a[3]), "r"(b[0]), "r"(b[1]));
}
__device__ __forceinline__ void cp16(uint32_t smem_dst, const void* gsrc) {
    asm volatile("cp.async.cg.shared.global [%0], [%1], 16;"
                 :: "r"(smem_dst), "l"(gsrc));
}
#define CP_COMMIT() asm volatile("cp.async.commit_group;" ::: "memory")
#define CP_WAIT1()  asm volatile("cp.async.wait_group 1;"  ::: "memory")
#define CP_WAIT0()  asm volatile("cp.async.wait_group 0;"  ::: "memory")

// ---------------------------------------------------------------------------
// 0) W prepass: W[768,256] f32 -> g_Wh[256 n][768 k] f16 (transpose+convert)
// ---------------------------------------------------------------------------
__global__ __launch_bounds__(256) void wprep_kernel(const float* __restrict__ W) {
    __shared__ float t[32][33];
    int kb = blockIdx.x * 32, nb = blockIdx.y * 32;
    int tx = threadIdx.x & 31, ty = threadIdx.x >> 5;   // 32 x 8
    #pragma unroll
    for (int i = 0; i < 32; i += 8)
        t[ty + i][tx] = W[(kb + ty + i) * CCH + nb + tx];
    __syncthreads();
    #pragma unroll
    for (int i = 0; i < 32; i += 8)
        g_Wh[(nb + ty + i) * KDIM + kb + tx] = __float2half_rn(t[tx][ty + i]);
    cudaTriggerProgrammaticLaunchCompletion();
}

// ---------------------------------------------------------------------------
// 1) Conv-as-GEMM, fused im2col, fp16 m16n8k16 mma, 3-stage cp.async,
//    single barrier per chunk. CTA tile 128x128, 8 warps each 64x32.
// ---------------------------------------------------------------------------
#define BK      32
#define NCH     (KDIM / BK)          // 24
#define LDA     40                   // floats per A row (32 data + 8 pad)
#define LDBT    40                   // halves per B row (32 data + 8 pad)
#define A_BYTES (128 * LDA * 4)      // 20480
#define B_BYTES (128 * LDBT * 2)     // 10240
#define STG_BYTES (A_BYTES + B_BYTES)// 30720
#define STAGES  3
#define SMEM_BYTES (STAGES * STG_BYTES)   // 92160

__global__ __launch_bounds__(256, 2) void conv_mma_kernel(
    const float* __restrict__ img,     // [16,512,512,3]
    const float* __restrict__ bias)    // [256]
{
    extern __shared__ float smem[];
    const uint32_t sb = smem_to_u32(smem);

    const int tid = threadIdx.x;
    const int wid = tid >> 5;
    const int lid = tid & 31;
    const int g   = lid >> 2;          // 0..7
    const int t4  = lid & 3;           // 0..3
    const int wm  = wid & 1;           // 2 warps in M
    const int wn  = wid >> 1;          // 4 warps in N

    const int n0 = blockIdx.x * 128;
    const int m0 = blockIdx.y * 128;

    // cp.async source bases (independent prologue math)
    const float* aBase[4];
    #pragma unroll
    for (int i = 0; i < 4; i++) {
        int f4  = tid + i * 256;               // 0..1023
        int row = f4 >> 3;                     // 0..127
        int m   = m0 + row;
        int b   = m >> 10;
        int oy  = (m >> 5) & 31;
        int ox  = m & 31;
        aBase[i] = img + (size_t)((b * 512 + oy * 16) * 512 + ox * 16) * 3;
    }
    const __half* bBase[2];
    #pragma unroll
    for (int i = 0; i < 2; i++) {
        int f4  = tid + i * 256;               // 0..511
        int row = f4 >> 2;                     // 0..127
        int q   = f4 & 3;
        bBase[i] = g_Wh + (size_t)(n0 + row) * KDIM + q * 8;
    }

    auto issue = [&](int c) {
        const int k0 = c * BK;
        const uint32_t soff = sb + (uint32_t)(c % STAGES) * STG_BYTES;
        #pragma unroll
        for (int i = 0; i < 4; i++) {
            int f4  = tid + i * 256;
            int row = f4 >> 3;
            int q   = f4 & 7;
            int k   = k0 + q * 4;
            int ky  = k / 48;
            int rem = k - ky * 48;             // 4 | 48 -> never crosses pixel run
            cp16(soff + (uint32_t)(row * (LDA * 4) + q * 16),
                 aBase[i] + ky * 1536 + rem);
        }
        #pragma unroll
        for (int i = 0; i < 2; i++) {
            int f4  = tid + i * 256;
            int row = f4 >> 2;
            int q   = f4 & 3;
            cp16(soff + (uint32_t)(A_BYTES + row * (LDBT * 2) + q * 16),
                 bBase[i] + k0);
        }
        CP_COMMIT();
    };

    float acc[4][4][4];
    #pragma unroll
    for (int i = 0; i < 4; i++)
        #pragma unroll
        for (int j = 0; j < 4; j++)
            #pragma unroll
            for (int r = 0; r < 4; r++) acc[i][j][r] = 0.f;

    // wait for wprep's g_Wh before the first B load
    cudaGridDependencySynchronize();

    // prologue: 2 chunks in flight
    issue(0); issue(1);

    for (int c = 0; c < NCH; c++) {
        if (c + 1 < NCH) CP_WAIT1(); else CP_WAIT0();
        __syncthreads();                       // frees stage (c+2)%3, chunk c visible
        if (c + 2 < NCH) issue(c + 2);

        const float*    As  = smem + (c % STAGES) * (STG_BYTES / 4);
        const uint32_t* Bsu = (const uint32_t*)((const char*)As + A_BYTES);

        #pragma unroll
        for (int kk = 0; kk < 2; kk++) {       // two k16 steps per chunk
            const int ka = kk * 16 + 2 * t4;   // A k offset (floats)
            uint32_t afr[4][4], bfr[4][2];
            #pragma unroll
            for (int mi = 0; mi < 4; mi++) {
                int mr = wm * 64 + mi * 16 + g;
                float2 v0 = *(const float2*)&As[mr * LDA + ka];
                float2 v1 = *(const float2*)&As[(mr + 8) * LDA + ka];
                float2 v2 = *(const float2*)&As[mr * LDA + ka + 8];
                float2 v3 = *(const float2*)&As[(mr + 8) * LDA + ka + 8];
                afr[mi][0] = f2h2(v0.x, v0.y);
                afr[mi][1] = f2h2(v1.x, v1.y);
                afr[mi][2] = f2h2(v2.x, v2.y);
                afr[mi][3] = f2h2(v3.x, v3.y);
            }
            #pragma unroll
            for (int ni = 0; ni < 4; ni++) {
                int nc = wn * 32 + ni * 8 + g;
                bfr[ni][0] = Bsu[nc * (LDBT / 2) + kk * 8 + t4];
                bfr[ni][1] = Bsu[nc * (LDBT / 2) + kk * 8 + t4 + 4];
            }
            #pragma unroll
            for (int mi = 0; mi < 4; mi++)
                #pragma unroll
                for (int ni = 0; ni < 4; ni++)
                    mma_f16(acc[mi][ni], afr[mi], bfr[ni]);
        }
    }

    // epilogue: bias + relu -> g_feat (f16)
    #pragma unroll
    for (int mi = 0; mi < 4; mi++) {
        #pragma unroll
        for (int ni = 0; ni < 4; ni++) {
            int m = m0 + wm * 64 + mi * 16 + g;
            int n = n0 + wn * 32 + ni * 8 + 2 * t4;
            float b0 = bias[n], b1 = bias[n + 1];
            __half2 h0 = __floats2half2_rn(fmaxf(acc[mi][ni][0] + b0, 0.f),
                                           fmaxf(acc[mi][ni][1] + b1, 0.f));
            __half2 h1 = __floats2half2_rn(fmaxf(acc[mi][ni][2] + b0, 0.f),
                                           fmaxf(acc[mi][ni][3] + b1, 0.f));
            *(__half2*)&g_feat[(size_t)m * CCH + n]       = h0;
            *(__half2*)&g_feat[(size_t)(m + 8) * CCH + n] = h1;
        }
    }
    cudaTriggerProgrammaticLaunchCompletion();
}

// ---------------------------------------------------------------------------
// 2) ROI align v3 — compile-time unrolled, full-MLP.
//    Warp w (<7) owns sample row i=w: the j-loop (7 samples) is fully
//    unrolled with constant steps (no int division); all 28 uint4 corner
//    loads are independent and issued before consumption (MLP~28 vs ~4
//    serial exposures before). Warp 7 zeroes its partial row.
// ---------------------------------------------------------------------------
__global__ __launch_bounds__(256) void roi_kernel(const float* __restrict__ boxes) {
    __shared__ float sPart[8][CCH];            // 8KB partials
    const int roi  = blockIdx.x;
    const int b    = roi >> 4;
    const int tid  = threadIdx.x;
    const int w    = tid >> 5;
    const int lane = tid & 31;
    const int coff = lane * 8;                 // 8 channels per lane

    float4 box = *(const float4*)&boxes[roi * 4];
    float ymin = box.x, xmin = box.y, ymax = box.z, xmax = box.w;
    bool empty = (ymin == -1.f) && (xmin == -1.f) && (ymax == -1.f) && (xmax == -1.f);
    if (empty) {
        g_obj[(size_t)roi * CCH + tid] = 0.f;
        cudaTriggerProgrammaticLaunchCompletion();
        return;
    }

    const __half* fb = g_feat + (size_t)b * FH * FW * CCH;

    // wait for conv's g_feat
    cudaGridDependencySynchronize();

    if (w < 7) {
        // y coordinates for row i = w (uniform per warp)
        const float stepy = ((float)w + 0.5f) * (1.f / (float)S_ROI);
        float py = (ymin + (ymax - ymin) * stepy) * (float)FH - 0.5f;
        float y0f = floorf(py);
        float wy = py - y0f;
        int yi = (int)y0f;
        int y0 = min(max(yi, 0), FH - 1);
        int y1 = min(max(yi + 1, 0), FH - 1);
        const __half* ry0 = fb + y0 * (FW * CCH);
        const __half* ry1 = fb + y1 * (FW * CCH);

        // x coords for all 7 columns (compile-time steps)
        float wxv[7], w00[7], w01[7], w10[7], w11[7];
        int x0v[7], x1v[7];
        #pragma unroll
        for (int j = 0; j < 7; j++) {
            const float stepx = ((float)j + 0.5f) * (1.f / (float)S_ROI);
            float px = (xmin + (xmax - xmin) * stepx) * (float)FW - 0.5f;
            float x0f = floorf(px);
            float wx = px - x0f;
            int xi = (int)x0f;
            x0v[j] = min(max(xi, 0), FW - 1);
            x1v[j] = min(max(xi + 1, 0), FW - 1);
            wxv[j] = wx;
            w00[j] = (1.f - wy) * (1.f - wx);
            w01[j] = (1.f - wy) * wx;
            w10[j] = wy * (1.f - wx);
            w11[j] = wy * wx;
        }

        // issue all 28 corner loads (independent)
        uint4 f00[7], f01[7], f10[7], f11[7];
        #pragma unroll
        for (int j = 0; j < 7; j++) {
            f00[j] = *(const uint4*)(ry0 + x0v[j] * CCH + coff);
            f01[j] = *(const uint4*)(ry0 + x1v[j] * CCH + coff);
            f10[j] = *(const uint4*)(ry1 + x0v[j] * CCH + coff);
            f11[j] = *(const uint4*)(ry1 + x1v[j] * CCH + coff);
        }

        float accv[8];
        #pragma unroll
        for (int q = 0; q < 8; q++) accv[q] = 0.f;

        #pragma unroll
        for (int j = 0; j < 7; j++) {
            const __half2* h00 = (const __half2*)&f00[j];
            const __half2* h01 = (const __half2*)&f01[j];
            const __half2* h10 = (const __half2*)&f10[j];
            const __half2* h11 = (const __half2*)&f11[j];
            #pragma unroll
            for (int q = 0; q < 4; q++) {
                float2 a = __half22float2(h00[q]);
                float2 c = __half22float2(h01[q]);
                float2 d = __half22float2(h10[q]);
                float2 e = __half22float2(h11[q]);
                accv[2 * q]     += w00[j] * a.x + w01[j] * c.x + w10[j] * d.x + w11[j] * e.x;
                accv[2 * q + 1] += w00[j] * a.y + w01[j] * c.y + w10[j] * d.y + w11[j] * e.y;
            }
        }

        *(float4*)&sPart[w][coff]     = *(float4*)&accv[0];
        *(float4*)&sPart[w][coff + 4] = *(float4*)&accv[4];
    } else {
        float4 z = {0.f, 0.f, 0.f, 0.f};
        *(float4*)&sPart[7][coff]     = z;
        *(float4*)&sPart[7][coff + 4] = z;
    }
    __syncthreads();

    float tot = 0.f;
    #pragma unroll
    for (int ww = 0; ww < 8; ww++) tot += sPart[ww][tid];
    g_obj[(size_t)roi * CCH + tid] = tot * (1.f / (S_ROI * S_ROI));
    cudaTriggerProgrammaticLaunchCompletion();
}

// ---------------------------------------------------------------------------
// 3) Dense: out[256,256] = obj[256,256] @ Wd[256,256] + bd.
//    128 blocks x 2 rows, Wd via 3-stage cp.async pipeline, DK=32
//    (measured best). First two stages prefetch before the PDL sync.
// ---------------------------------------------------------------------------
#define DK        32                          // k-rows per stage
#define DNSTG     (CCH / DK)                  // 8 stages
#define DSTG_FLT  (DK * DDIM)                 // 8192 floats / stage
#define DSMEM_BYTES ((3 * DSTG_FLT + 2 * CCH) * 4)   // 100352

__global__ __launch_bounds__(256) void dense_kernel(
    const float* __restrict__ Wd, const float* __restrict__ bd,
    float* __restrict__ out)
{
    extern __shared__ float s[];
    float* sW   = s;                          // [3][DK*DDIM]
    float* sObj = s + 3 * DSTG_FLT;           // [2][CCH]
    const uint32_t sb = smem_to_u32(s);

    const int tid = threadIdx.x;
    const int r0  = blockIdx.x * 2;

    auto issueW = [&](int st) {
        const uint32_t soff = sb + (uint32_t)(st % 3) * (DSTG_FLT * 4);
        const int k0 = st * DK;
        #pragma unroll
        for (int i = 0; i < 8; i++) {
            int f4  = tid + i * 256;           // 0..2047
            int row = f4 >> 6;                 // 0..31
            int q   = f4 & 63;
            cp16(soff + (uint32_t)(row * DDIM + q * 4) * 4,
                 Wd + (size_t)(k0 + row) * DDIM + q * 4);
        }
        CP_COMMIT();
    };

    // Wd and bd are kernel inputs — independent of roi; prefetch early.
    issueW(0); issueW(1);
    const float bb = bd[tid];

    // wait for roi's g_obj
    cudaGridDependencySynchronize();

    sObj[tid]       = g_obj[(size_t)r0 * CCH + tid];
    sObj[CCH + tid] = g_obj[(size_t)(r0 + 1) * CCH + tid];
    __syncthreads();

    float acc0 = 0.f, acc1 = 0.f;
    for (int st = 0; st < DNSTG; st++) {
        if (st + 1 < DNSTG) CP_WAIT1(); else CP_WAIT0();
        __syncthreads();
        if (st + 2 < DNSTG) issueW(st + 2);

        const float* w = sW + (st % 3) * DSTG_FLT;
        const int k0 = st * DK;
        #pragma unroll
        for (int k = 0; k < DK; k++) {
            float wv = w[k * DDIM + tid];
            acc0 += sObj[k0 + k] * wv;
            acc1 += sObj[CCH + k0 + k] * wv;
        }
    }

    out[(size_t)r0 * DDIM + tid]       = acc0 + bb;
    out[(size_t)(r0 + 1) * DDIM + tid] = acc1 + bb;
}

// ---------------------------------------------------------------------------
// Launch — PDL chain: wprep -> conv -> roi -> dense
// ---------------------------------------------------------------------------
static void launch_pdl(const void* fn, dim3 grid, dim3 block, size_t smem,
                       void** args) {
    cudaLaunchConfig_t cfg = {};
    cfg.gridDim = grid;
    cfg.blockDim = block;
    cfg.dynamicSmemBytes = smem;
    cfg.stream = 0;
    cudaLaunchAttribute attr[1];
    attr[0].id = cudaLaunchAttributeProgrammaticStreamSerialization;
    attr[0].val.programmaticStreamSerializationAllowed = 1;
    cfg.attrs = attr;
    cfg.numAttrs = 1;
    cudaLaunchKernelExC(&cfg, fn, args);
}

extern "C" void kernel_launch(void* const* d_in, const int* in_sizes, int n_in,
                              void* d_out, int out_size) {
    const float* images  = (const float*)d_in[0];
    const float* bboxes  = (const float*)d_in[1];
    const float* conv_w  = (const float*)d_in[2];
    const float* conv_b  = (const float*)d_in[3];
    const float* dense_w = (const float*)d_in[4];
    const float* dense_b = (const float*)d_in[5];
    float* out = (float*)d_out;

    static bool attr_set = false;
    if (!attr_set) {
        cudaFuncSetAttribute(conv_mma_kernel,
                             cudaFuncAttributeMaxDynamicSharedMemorySize, SMEM_BYTES);
        cudaFuncSetAttribute(dense_kernel,
                             cudaFuncAttributeMaxDynamicSharedMemorySize, DSMEM_BYTES);
        attr_set = true;
    }

    dim3 wgrid(KDIM / 32, CCH / 32);     // (24, 8)
    wprep_kernel<<<wgrid, 256>>>(conv_w);

    {
        void* args[] = {(void*)&images, (void*)&conv_b};
        launch_pdl((const void*)conv_mma_kernel,
                   dim3(CCH / 128, M_TOT / 128), dim3(256), SMEM_BYTES, args);
    }
    {
        void* args[] = {(void*)&bboxes};
        launch_pdl((const void*)roi_kernel,
                   dim3(BDIM * NBOX), dim3(256), 0, args);
    }
    {
        void* args[] = {(void*)&dense_w, (void*)&dense_b, (void*)&out};
        launch_pdl((const void*)dense_kernel,
                   dim3((BDIM * NBOX) / 2), dim3(256), DSMEM_BYTES, args);
    }
}

// round 17
// speedup vs baseline: 1.6237x; 1.0159x over previous
#include <cuda_runtime.h>
#include <cuda_fp16.h>
#include <cstdint>

// ---------------------------------------------------------------------------
// Problem constants
// ---------------------------------------------------------------------------
#define BDIM   16
#define FH     32
#define FW     32
#define NBOX   16
#define CCH    256     // conv out channels
#define DDIM   256     // dense out
#define KDIM   768     // 16*16*3
#define M_TOT  16384   // B*32*32
#define S_ROI  7

// Scratch (static __device__ — no allocations allowed)
__device__ __half g_Wh[CCH * KDIM];          // conv W transposed+f16: [256 n][768 k]
__device__ __half g_Wdh[DDIM * DDIM];        // dense W f16: [256 k][256 n]
__device__ __half g_feat[M_TOT * CCH];       // conv+relu feat [16384, 256] f16
__device__ float  g_obj[BDIM * NBOX * CCH];  // pooled rois   [256, 256]

// ---------------------------------------------------------------------------
// helpers
// ---------------------------------------------------------------------------
__device__ __forceinline__ uint32_t smem_to_u32(const void* smem_ptr) {
    uint32_t addr;
    asm("{ .reg .u64 tmp; cvta.to.shared.u64 tmp, %1; cvt.u32.u64 %0, tmp; }"
        : "=r"(addr) : "l"(smem_ptr));
    return addr;
}
__device__ __forceinline__ uint32_t f2h2(float lo, float hi) {
    uint32_t r;
    asm("cvt.rn.f16x2.f32 %0, %1, %2;" : "=r"(r) : "f"(hi), "f"(lo));
    return r;
}
__device__ __forceinline__ void mma_f16(float* d, const uint32_t* a, const uint32_t* b) {
    asm volatile(
        "mma.sync.aligned.m16n8k16.row.col.f32.f16.f16.f32 "
        "{%0,%1,%2,%3}, {%4,%5,%6,%7}, {%8,%9}, {%0,%1,%2,%3};"
        : "+f"(d[0]), "+f"(d[1]), "+f"(d[2]), "+f"(d[3])
        : "r"(a[0]), "r"(a[1]), "r"(a[2]), "r"(a[3]), "r"(b[0]), "r"(b[1]));
}
__device__ __forceinline__ void cp16(uint32_t smem_dst, const void* gsrc) {
    asm volatile("cp.async.cg.shared.global [%0], [%1], 16;"
                 :: "r"(smem_dst), "l"(gsrc));
}
#define CP_COMMIT() asm volatile("cp.async.commit_group;" ::: "memory")
#define CP_WAIT1()  asm volatile("cp.async.wait_group 1;"  ::: "memory")
#define CP_WAIT0()  asm volatile("cp.async.wait_group 0;"  ::: "memory")
template<int N> __device__ __forceinline__ void cp_wait_n() {
    asm volatile("cp.async.wait_group %0;" :: "n"(N) : "memory");
}

// ---------------------------------------------------------------------------
// 0) Weight prep (one launch):
//    blocks x<24: conv W[768,256] f32 -> g_Wh[256 n][768 k] f16 (transpose)
//    blocks x>=24: dense Wd[256,256] f32 -> g_Wdh f16 (straight convert)
// ---------------------------------------------------------------------------
__global__ __launch_bounds__(256) void wprep_kernel(const float* __restrict__ W,
                                                    const float* __restrict__ Wd) {
    if (blockIdx.x < 24) {
        __shared__ float t[32][33];
        int kb = blockIdx.x * 32, nb = blockIdx.y * 32;
        int tx = threadIdx.x & 31, ty = threadIdx.x >> 5;   // 32 x 8
        #pragma unroll
        for (int i = 0; i < 32; i += 8)
            t[ty + i][tx] = W[(kb + ty + i) * CCH + nb + tx];
        __syncthreads();
        #pragma unroll
        for (int i = 0; i < 32; i += 8)
            g_Wh[(nb + ty + i) * KDIM + kb + tx] = __float2half_rn(t[tx][ty + i]);
    } else {
        // 8 x-slots (24..31) x 8 y = 64 blocks; 1024 elements each
        int t = (blockIdx.x - 24) + blockIdx.y * 8;         // 0..63
        int base = t * 1024 + threadIdx.x * 4;
        float4 v = *(const float4*)&Wd[base];
        __half2 h0 = __floats2half2_rn(v.x, v.y);
        __half2 h1 = __floats2half2_rn(v.z, v.w);
        *(__half2*)&g_Wdh[base]     = h0;
        *(__half2*)&g_Wdh[base + 2] = h1;
    }
    cudaTriggerProgrammaticLaunchCompletion();
}

// ---------------------------------------------------------------------------
// 1) Conv-as-GEMM, fused im2col, fp16 m16n8k16 mma, 3-stage cp.async,
//    single barrier per chunk. CTA tile 128x128, 8 warps each 64x32.
// ---------------------------------------------------------------------------
#define BK      32
#define NCH     (KDIM / BK)          // 24
#define LDA     40                   // floats per A row (32 data + 8 pad)
#define LDBT    40                   // halves per B row (32 data + 8 pad)
#define A_BYTES (128 * LDA * 4)      // 20480
#define B_BYTES (128 * LDBT * 2)     // 10240
#define STG_BYTES (A_BYTES + B_BYTES)// 30720
#define STAGES  3
#define SMEM_BYTES (STAGES * STG_BYTES)   // 92160

__global__ __launch_bounds__(256, 2) void conv_mma_kernel(
    const float* __restrict__ img,     // [16,512,512,3]
    const float* __restrict__ bias)    // [256]
{
    extern __shared__ float smem[];
    const uint32_t sb = smem_to_u32(smem);

    const int tid = threadIdx.x;
    const int wid = tid >> 5;
    const int lid = tid & 31;
    const int g   = lid >> 2;          // 0..7
    const int t4  = lid & 3;           // 0..3
    const int wm  = wid & 1;           // 2 warps in M
    const int wn  = wid >> 1;          // 4 warps in N

    const int n0 = blockIdx.x * 128;
    const int m0 = blockIdx.y * 128;

    // cp.async source bases (independent prologue math)
    const float* aBase[4];
    #pragma unroll
    for (int i = 0; i < 4; i++) {
        int f4  = tid + i * 256;               // 0..1023
        int row = f4 >> 3;                     // 0..127
        int m   = m0 + row;
        int b   = m >> 10;
        int oy  = (m >> 5) & 31;
        int ox  = m & 31;
        aBase[i] = img + (size_t)((b * 512 + oy * 16) * 512 + ox * 16) * 3;
    }
    const __half* bBase[2];
    #pragma unroll
    for (int i = 0; i < 2; i++) {
        int f4  = tid + i * 256;               // 0..511
        int row = f4 >> 2;                     // 0..127
        int q   = f4 & 3;
        bBase[i] = g_Wh + (size_t)(n0 + row) * KDIM + q * 8;
    }

    auto issue = [&](int c) {
        const int k0 = c * BK;
        const uint32_t soff = sb + (uint32_t)(c % STAGES) * STG_BYTES;
        #pragma unroll
        for (int i = 0; i < 4; i++) {
            int f4  = tid + i * 256;
            int row = f4 >> 3;
            int q   = f4 & 7;
            int k   = k0 + q * 4;
            int ky  = k / 48;
            int rem = k - ky * 48;             // 4 | 48 -> never crosses pixel run
            cp16(soff + (uint32_t)(row * (LDA * 4) + q * 16),
                 aBase[i] + ky * 1536 + rem);
        }
        #pragma unroll
        for (int i = 0; i < 2; i++) {
            int f4  = tid + i * 256;
            int row = f4 >> 2;
            int q   = f4 & 3;
            cp16(soff + (uint32_t)(A_BYTES + row * (LDBT * 2) + q * 16),
                 bBase[i] + k0);
        }
        CP_COMMIT();
    };

    float acc[4][4][4];
    #pragma unroll
    for (int i = 0; i < 4; i++)
        #pragma unroll
        for (int j = 0; j < 4; j++)
            #pragma unroll
            for (int r = 0; r < 4; r++) acc[i][j][r] = 0.f;

    // wait for wprep's g_Wh before the first B load
    cudaGridDependencySynchronize();

    // prologue: 2 chunks in flight
    issue(0); issue(1);

    for (int c = 0; c < NCH; c++) {
        if (c + 1 < NCH) CP_WAIT1(); else CP_WAIT0();
        __syncthreads();                       // frees stage (c+2)%3, chunk c visible
        if (c + 2 < NCH) issue(c + 2);

        const float*    As  = smem + (c % STAGES) * (STG_BYTES / 4);
        const uint32_t* Bsu = (const uint32_t*)((const char*)As + A_BYTES);

        #pragma unroll
        for (int kk = 0; kk < 2; kk++) {       // two k16 steps per chunk
            const int ka = kk * 16 + 2 * t4;   // A k offset (floats)
            uint32_t afr[4][4], bfr[4][2];
            #pragma unroll
            for (int mi = 0; mi < 4; mi++) {
                int mr = wm * 64 + mi * 16 + g;
                float2 v0 = *(const float2*)&As[mr * LDA + ka];
                float2 v1 = *(const float2*)&As[(mr + 8) * LDA + ka];
                float2 v2 = *(const float2*)&As[mr * LDA + ka + 8];
                float2 v3 = *(const float2*)&As[(mr + 8) * LDA + ka + 8];
                afr[mi][0] = f2h2(v0.x, v0.y);
                afr[mi][1] = f2h2(v1.x, v1.y);
                afr[mi][2] = f2h2(v2.x, v2.y);
                afr[mi][3] = f2h2(v3.x, v3.y);
            }
            #pragma unroll
            for (int ni = 0; ni < 4; ni++) {
                int nc = wn * 32 + ni * 8 + g;
                bfr[ni][0] = Bsu[nc * (LDBT / 2) + kk * 8 + t4];
                bfr[ni][1] = Bsu[nc * (LDBT / 2) + kk * 8 + t4 + 4];
            }
            #pragma unroll
            for (int mi = 0; mi < 4; mi++)
                #pragma unroll
                for (int ni = 0; ni < 4; ni++)
                    mma_f16(acc[mi][ni], afr[mi], bfr[ni]);
        }
    }

    // epilogue: bias + relu -> g_feat (f16)
    #pragma unroll
    for (int mi = 0; mi < 4; mi++) {
        #pragma unroll
        for (int ni = 0; ni < 4; ni++) {
            int m = m0 + wm * 64 + mi * 16 + g;
            int n = n0 + wn * 32 + ni * 8 + 2 * t4;
            float b0 = bias[n], b1 = bias[n + 1];
            __half2 h0 = __floats2half2_rn(fmaxf(acc[mi][ni][0] + b0, 0.f),
                                           fmaxf(acc[mi][ni][1] + b1, 0.f));
            __half2 h1 = __floats2half2_rn(fmaxf(acc[mi][ni][2] + b0, 0.f),
                                           fmaxf(acc[mi][ni][3] + b1, 0.f));
            *(__half2*)&g_feat[(size_t)m * CCH + n]       = h0;
            *(__half2*)&g_feat[(size_t)(m + 8) * CCH + n] = h1;
        }
    }
    cudaTriggerProgrammaticLaunchCompletion();
}

// ---------------------------------------------------------------------------
// 2) ROI align v3 — compile-time unrolled, full-MLP.
// ---------------------------------------------------------------------------
__global__ __launch_bounds__(256) void roi_kernel(const float* __restrict__ boxes) {
    __shared__ float sPart[8][CCH];            // 8KB partials
    const int roi  = blockIdx.x;
    const int b    = roi >> 4;
    const int tid  = threadIdx.x;
    const int w    = tid >> 5;
    const int lane = tid & 31;
    const int coff = lane * 8;                 // 8 channels per lane

    float4 box = *(const float4*)&boxes[roi * 4];
    float ymin = box.x, xmin = box.y, ymax = box.z, xmax = box.w;
    bool empty = (ymin == -1.f) && (xmin == -1.f) && (ymax == -1.f) && (xmax == -1.f);
    if (empty) {
        g_obj[(size_t)roi * CCH + tid] = 0.f;
        cudaTriggerProgrammaticLaunchCompletion();
        return;
    }

    const __half* fb = g_feat + (size_t)b * FH * FW * CCH;

    if (w < 7) {
        // y coordinates for row i = w (uniform per warp)
        const float stepy = ((float)w + 0.5f) * (1.f / (float)S_ROI);
        float py = (ymin + (ymax - ymin) * stepy) * (float)FH - 0.5f;
        float y0f = floorf(py);
        float wy = py - y0f;
        int yi = (int)y0f;
        int y0 = min(max(yi, 0), FH - 1);
        int y1 = min(max(yi + 1, 0), FH - 1);
        const __half* ry0 = fb + y0 * (FW * CCH);
        const __half* ry1 = fb + y1 * (FW * CCH);

        // x coords for all 7 columns (compile-time steps)
        float w00[7], w01[7], w10[7], w11[7];
        int x0v[7], x1v[7];
        #pragma unroll
        for (int j = 0; j < 7; j++) {
            const float stepx = ((float)j + 0.5f) * (1.f / (float)S_ROI);
            float px = (xmin + (xmax - xmin) * stepx) * (float)FW - 0.5f;
            float x0f = floorf(px);
            float wx = px - x0f;
            int xi = (int)x0f;
            x0v[j] = min(max(xi, 0), FW - 1);
            x1v[j] = min(max(xi + 1, 0), FW - 1);
            w00[j] = (1.f - wy) * (1.f - wx);
            w01[j] = (1.f - wy) * wx;
            w10[j] = wy * (1.f - wx);
            w11[j] = wy * wx;
        }

        // wait for conv's g_feat (as late as possible)
        cudaGridDependencySynchronize();

        // issue all 28 corner loads (independent)
        uint4 f00[7], f01[7], f10[7], f11[7];
        #pragma unroll
        for (int j = 0; j < 7; j++) {
            f00[j] = *(const uint4*)(ry0 + x0v[j] * CCH + coff);
            f01[j] = *(const uint4*)(ry0 + x1v[j] * CCH + coff);
            f10[j] = *(const uint4*)(ry1 + x0v[j] * CCH + coff);
            f11[j] = *(const uint4*)(ry1 + x1v[j] * CCH + coff);
        }

        float accv[8];
        #pragma unroll
        for (int q = 0; q < 8; q++) accv[q] = 0.f;

        #pragma unroll
        for (int j = 0; j < 7; j++) {
            const __half2* h00 = (const __half2*)&f00[j];
            const __half2* h01 = (const __half2*)&f01[j];
            const __half2* h10 = (const __half2*)&f10[j];
            const __half2* h11 = (const __half2*)&f11[j];
            #pragma unroll
            for (int q = 0; q < 4; q++) {
                float2 a = __half22float2(h00[q]);
                float2 c = __half22float2(h01[q]);
                float2 d = __half22float2(h10[q]);
                float2 e = __half22float2(h11[q]);
                accv[2 * q]     += w00[j] * a.x + w01[j] * c.x + w10[j] * d.x + w11[j] * e.x;
                accv[2 * q + 1] += w00[j] * a.y + w01[j] * c.y + w10[j] * d.y + w11[j] * e.y;
            }
        }

        *(float4*)&sPart[w][coff]     = *(float4*)&accv[0];
        *(float4*)&sPart[w][coff + 4] = *(float4*)&accv[4];
    } else {
        cudaGridDependencySynchronize();
        float4 z = {0.f, 0.f, 0.f, 0.f};
        *(float4*)&sPart[7][coff]     = z;
        *(float4*)&sPart[7][coff + 4] = z;
    }
    __syncthreads();

    float tot = 0.f;
    #pragma unroll
    for (int ww = 0; ww < 8; ww++) tot += sPart[ww][tid];
    g_obj[(size_t)roi * CCH + tid] = tot * (1.f / (S_ROI * S_ROI));
    cudaTriggerProgrammaticLaunchCompletion();
}

// ---------------------------------------------------------------------------
// 3) Dense v4 — FULL prefetch: all 8 f16 weight stages (128KB) issued via
//    cp.async BEFORE the PDL dependency sync (Wd independent of roi).
//    Compute loop has no exposed load latency: wait_group<7-st> on
//    long-in-flight data + one barrier per stage.
// ---------------------------------------------------------------------------
#define DK        32                          // k-rows per stage
#define DNSTG     (DDIM / DK)                 // 8 stages
#define DSTG_HALF (DK * DDIM)                 // 8192 halves / stage (16KB)
#define DSMEM_BYTES (DNSTG * DSTG_HALF * 2 + 2 * CCH * 4)   // 133120

__global__ __launch_bounds__(256) void dense_kernel(
    const float* __restrict__ bd,
    float* __restrict__ out)
{
    extern __shared__ char ds[];
    __half* sWh  = (__half*)ds;                       // [8][DK*DDIM] f16
    float*  sObj = (float*)(ds + DNSTG * DSTG_HALF * 2); // [2][CCH]
    const uint32_t sb = smem_to_u32(ds);

    const int tid = threadIdx.x;
    const int r0  = blockIdx.x * 2;

    // Prefetch ALL weight stages (f16; 1024 cp16 per stage = 4/thread)
    #pragma unroll
    for (int st = 0; st < DNSTG; st++) {
        const uint32_t soff = sb + (uint32_t)st * (DSTG_HALF * 2);
        const int k0 = st * DK;
        #pragma unroll
        for (int i = 0; i < 4; i++) {
            int f4  = tid + i * 256;           // 0..1023
            int row = f4 >> 5;                 // 0..31 (k row)
            int q   = f4 & 31;                 // 16B chunk (8 halves)
            cp16(soff + (uint32_t)(row * DDIM + q * 8) * 2,
                 g_Wdh + (size_t)(k0 + row) * DDIM + q * 8);
        }
        CP_COMMIT();
    }
    const float bb = bd[tid];

    // wait for roi's g_obj
    cudaGridDependencySynchronize();

    sObj[tid]       = g_obj[(size_t)r0 * CCH + tid];
    sObj[CCH + tid] = g_obj[(size_t)(r0 + 1) * CCH + tid];
    __syncthreads();

    float acc0 = 0.f, acc1 = 0.f;
    #pragma unroll
    for (int st = 0; st < DNSTG; st++) {
        switch (st) {   // wait_group immediate must be a literal
            case 0: cp_wait_n<7>(); break;
            case 1: cp_wait_n<6>(); break;
            case 2: cp_wait_n<5>(); break;
            case 3: cp_wait_n<4>(); break;
            case 4: cp_wait_n<3>(); break;
            case 5: cp_wait_n<2>(); break;
            case 6: cp_wait_n<1>(); break;
            default: cp_wait_n<0>(); break;
        }
        __syncthreads();
        const __half* wst = sWh + st * DSTG_HALF;
        const int k0 = st * DK;
        #pragma unroll
        for (int k = 0; k < DK; k++) {
            float wv = __half2float(wst[k * DDIM + tid]);
            acc0 += sObj[k0 + k] * wv;
            acc1 += sObj[CCH + k0 + k] * wv;
        }
    }

    out[(size_t)r0 * DDIM + tid]       = acc0 + bb;
    out[(size_t)(r0 + 1) * DDIM + tid] = acc1 + bb;
}

// ---------------------------------------------------------------------------
// Launch — PDL chain: wprep -> conv -> roi -> dense
// ---------------------------------------------------------------------------
static void launch_pdl(const void* fn, dim3 grid, dim3 block, size_t smem,
                       void** args) {
    cudaLaunchConfig_t cfg = {};
    cfg.gridDim = grid;
    cfg.blockDim = block;
    cfg.dynamicSmemBytes = smem;
    cfg.stream = 0;
    cudaLaunchAttribute attr[1];
    attr[0].id = cudaLaunchAttributeProgrammaticStreamSerialization;
    attr[0].val.programmaticStreamSerializationAllowed = 1;
    cfg.attrs = attr;
    cfg.numAttrs = 1;
    cudaLaunchKernelExC(&cfg, fn, args);
}

extern "C" void kernel_launch(void* const* d_in, const int* in_sizes, int n_in,
                              void* d_out, int out_size) {
    const float* images  = (const float*)d_in[0];
    const float* bboxes  = (const float*)d_in[1];
    const float* conv_w  = (const float*)d_in[2];
    const float* conv_b  = (const float*)d_in[3];
    const float* dense_w = (const float*)d_in[4];
    const float* dense_b = (const float*)d_in[5];
    float* out = (float*)d_out;

    static bool attr_set = false;
    if (!attr_set) {
        cudaFuncSetAttribute(conv_mma_kernel,
                             cudaFuncAttributeMaxDynamicSharedMemorySize, SMEM_BYTES);
        cudaFuncSetAttribute(dense_kernel,
                             cudaFuncAttributeMaxDynamicSharedMemorySize, DSMEM_BYTES);
        attr_set = true;
    }

    // prep: 24x8 W-transpose blocks + 8x8 Wd-convert blocks
    dim3 wgrid(32, 8);
    wprep_kernel<<<wgrid, 256>>>(conv_w, dense_w);

    {
        void* args[] = {(void*)&images, (void*)&conv_b};
        launch_pdl((const void*)conv_mma_kernel,
                   dim3(CCH / 128, M_TOT / 128), dim3(256), SMEM_BYTES, args);
    }
    {
        void* args[] = {(void*)&bboxes};
        launch_pdl((const void*)roi_kernel,
                   dim3(BDIM * NBOX), dim3(256), 0, args);
    }
    {
        void* args[] = {(void*)&dense_b, (void*)&out};
        launch_pdl((const void*)dense_kernel,
                   dim3((BDIM * NBOX) / 2), dim3(256), DSMEM_BYTES, args);
    }
}